// round 14
// baseline (speedup 1.0000x reference)
#include <cuda_runtime.h>

// out[(b*N+n)*D + c, s] = q[b, s, c] * w[n, c]
// q: (B=8, S=2048, D=256) fp32, c contiguous
// w: (N=20, D=256) fp32
// out: (B*N=160, D=256, S=2048) fp32, s contiguous
//
// R12 = R10 with NSPLIT=2 (halves redundant q reads) while keeping
// launch_bounds(256,8) for 8 CTAs/SM. Weights read from smem inside the
// store loop (instead of a 10-reg preload) to stay <=32 regs; at ~88% occ
// the LDS latency hides under TLP. Achieved traffic is ~6.9 TB/s of a
// mandatory 352 MB -> near the practical HBM ceiling.

#define BB 8
#define SS 2048
#define DD 256
#define NN 20
#define STILE 64
#define NSPLIT 2
#define NPB (NN / NSPLIT)   // 10 classes per block

__global__ __launch_bounds__(256, 8)
void FeatureReweightingModule_72447508349057_kernel(
    const float* __restrict__ q,
    const float* __restrict__ w,
    float* __restrict__ out)
{
    __shared__ float tile[STILE][33];   // [s_local][c_local], padded
    __shared__ float ws[NPB][32];       // 10x32 weight slice

    const int s0 = blockIdx.x * STILE;      // 32 s-tiles
    const int c0 = blockIdx.y << 5;         // 8 c-tiles
    const int b  = blockIdx.z >> 1;         // 8 batches
    const int n0 = (blockIdx.z & 1) * NPB;  // class half: 0 or 10

    const int tid = threadIdx.x;            // 256 threads

    // Stage the 10x32 weight slice (320 elems, 256 threads -> strided loop).
    #pragma unroll
    for (int i = tid; i < NPB * 32; i += 256) {
        ws[i >> 5][i & 31] = w[(n0 + (i >> 5)) * DD + c0 + (i & 31)];
    }

    // Load phase: 2 coalesced LDG.128 per thread along c.
    #pragma unroll
    for (int k = 0; k < 2; k++) {
        const int idx = tid + k * 256;
        const int sl  = idx >> 3;             // 0..63
        const int cq  = (idx & 7) << 2;       // 0,4,...,28
        const float4 v = *reinterpret_cast<const float4*>(
            &q[((size_t)b * SS + (s0 + sl)) * DD + c0 + cq]);
        tile[sl][cq + 0] = v.x;
        tile[sl][cq + 1] = v.y;
        tile[sl][cq + 2] = v.z;
        tile[sl][cq + 3] = v.w;
    }
    __syncthreads();

    // Transposed gather: two float4s of consecutive s for one c.
    // Banks (sq+i+cl) mod 32: all 32 distinct per warp -> conflict-free.
    const int cl = tid >> 3;                  // 0..31 (c within tile)
    const int sq = (tid & 7) << 2;            // 0,4,...,28
    float4 v0, v1;
    v0.x = tile[sq + 0][cl];
    v0.y = tile[sq + 1][cl];
    v0.z = tile[sq + 2][cl];
    v0.w = tile[sq + 3][cl];
    v1.x = tile[sq + 32][cl];
    v1.y = tile[sq + 33][cl];
    v1.z = tile[sq + 34][cl];
    v1.w = tile[sq + 35][cl];

    // Write phase: 20 streaming STG.128 per thread. Weight comes from smem
    // each iteration (1 LDS, 4 banks + broadcast): keeps regs <=32 for
    // 8 CTAs/SM; latency hidden by TLP at high occupancy.
    float* orow = out + ((size_t)((b * NN + n0)) * DD + c0 + cl) * SS + (s0 + sq);
    #pragma unroll
    for (int n = 0; n < NPB; n++) {
        const float sc = ws[n][cl];
        float4 o0, o1;
        o0.x = v0.x * sc; o0.y = v0.y * sc; o0.z = v0.z * sc; o0.w = v0.w * sc;
        o1.x = v1.x * sc; o1.y = v1.y * sc; o1.z = v1.z * sc; o1.w = v1.w * sc;
        float* p = orow + (size_t)n * DD * SS;
        __stcs(reinterpret_cast<float4*>(p), o0);
        __stcs(reinterpret_cast<float4*>(p + 32), o1);
    }
}

extern "C" void kernel_launch(void* const* d_in, const int* in_sizes, int n_in,
                              void* d_out, int out_size)
{
    const float* q = (const float*)d_in[0];   // (8, 2048, 256) fp32
    const float* w = (const float*)d_in[1];   // (20, 256) fp32
    float* out = (float*)d_out;               // (160, 256, 2048) fp32

    dim3 grid(SS / STILE, DD / 32, BB * NSPLIT);   // (32, 8, 16) = 4096 blocks
    FeatureReweightingModule_72447508349057_kernel<<<grid, 256>>>(q, w, out);
}

// round 16
// speedup vs baseline: 1.0120x; 1.0120x over previous
#include <cuda_runtime.h>

// out[(b*N+n)*D + c, s] = q[b, s, c] * w[n, c]
// q: (B=8, S=2048, D=256) fp32, c contiguous
// w: (20, 256) fp32
// out: (160, 256, 2048) fp32, s contiguous
//
// R14: warp-per-row store layout. Tile = 128 s x 8 c, smem holds the tile
// TRANSPOSED (tile_t[c][s]) so the gather is one LDS.128 and each warp owns
// one output channel: every STG.128 instruction writes 512B of one row
// contiguously (vs 256B over 2 instrs before) -> better DRAM row locality
// for the write stream. NSPLIT=1: q read exactly once.

#define BB 8
#define SS 2048
#define DD 256
#define NN 20
#define STILE 128
#define CTILE 8
#define TPAD 4   // tile_t row stride = 132 floats

__global__ __launch_bounds__(256)
void FeatureReweightingModule_72447508349057_kernel(
    const float* __restrict__ q,
    const float* __restrict__ w,
    float* __restrict__ out)
{
    __shared__ float tile_t[CTILE][STILE + TPAD];  // transposed: [c][s]
    __shared__ float ws[NN][CTILE];                // 20 x 8 weight slice

    const int s0 = blockIdx.x * STILE;   // 16 s-tiles
    const int c0 = blockIdx.y * CTILE;   // 32 c-tiles
    const int b  = blockIdx.z;           // 8 batches

    const int tid  = threadIdx.x;        // 256 threads
    const int lane = tid & 31;
    const int warp = tid >> 5;           // 0..7 -> channel within tile

    // Stage the 20x8 weight slice (160 elems <= 256 threads).
    if (tid < NN * CTILE) {
        ws[tid >> 3][tid & 7] = w[(tid >> 3) * DD + c0 + (tid & 7)];
    }

    // Load phase: 1 coalesced LDG.128 per thread (4 channels of one s),
    // scattered into the transposed tile with 4 conflict-free STS.32
    // (bank = (16(l&1) + (l>>1) + 4i + 16w) mod 32: all 32 distinct).
    {
        const int sl = tid >> 1;             // 0..127
        const int cq = (tid & 1) << 2;       // 0 or 4
        const float4 v = *reinterpret_cast<const float4*>(
            &q[((size_t)b * SS + s0 + sl) * DD + c0 + cq]);
        tile_t[cq + 0][sl] = v.x;
        tile_t[cq + 1][sl] = v.y;
        tile_t[cq + 2][sl] = v.z;
        tile_t[cq + 3][sl] = v.w;
    }
    __syncthreads();

    // Gather: one LDS.128 of 4 consecutive s at this warp's channel.
    // (8 lanes per 128B phase -> conflict-free; 132*4B row stride is 16B-aligned.)
    const float4 v = *reinterpret_cast<const float4*>(&tile_t[warp][lane << 2]);

    // Weights for this channel in registers (broadcast LDS, conflict-free).
    float wreg[NN];
    #pragma unroll
    for (int n = 0; n < NN; n++) wreg[n] = ws[n][warp];

    // Write phase: 20 streaming STG.128; a warp's 32 lanes cover 128
    // consecutive s -> 512B contiguous per row per class in one instruction.
    float* orow = out + ((size_t)(b * NN) * DD + c0 + warp) * SS + s0 + (lane << 2);
    #pragma unroll
    for (int n = 0; n < NN; n++) {
        const float sc = wreg[n];
        float4 o;
        o.x = v.x * sc;
        o.y = v.y * sc;
        o.z = v.z * sc;
        o.w = v.w * sc;
        __stcs(reinterpret_cast<float4*>(orow + (size_t)n * DD * SS), o);
    }
}

extern "C" void kernel_launch(void* const* d_in, const int* in_sizes, int n_in,
                              void* d_out, int out_size)
{
    const float* q = (const float*)d_in[0];   // (8, 2048, 256) fp32
    const float* w = (const float*)d_in[1];   // (20, 256) fp32
    float* out = (float*)d_out;               // (160, 256, 2048) fp32

    dim3 grid(SS / STILE, DD / CTILE, BB);    // (16, 32, 8) = 4096 blocks
    FeatureReweightingModule_72447508349057_kernel<<<grid, 256>>>(q, w, out);
}